// round 10
// baseline (speedup 1.0000x reference)
#include <cuda_runtime.h>
#include <cuda_bf16.h>

#define BB 64
#define NN 256
#define DD 6
#define SS 8                       // slices per batch -> 512 blocks total
#define NBLK (BB * SS)
#define EPSF 1e-8f
#define GOLDENF 1.618f
#define SENT 3.0e8f                // sentinel coordinate for masked elements

// Deterministic scratch (no FP atomics; counter only signals readiness).
__device__ float g_batch[BB][11];
__device__ float g_pair[NBLK][3];
__device__ int   g_count = 0;

__device__ __forceinline__ float warpSum(float v) {
#pragma unroll
    for (int o = 16; o > 0; o >>= 1) v += __shfl_down_sync(0xffffffffu, v, o);
    return v;
}

// ---------------------------------------------------------------------------
// Single fused kernel. grid = (BB, SS), block = 256.
//  - all blocks: pairwise terms (ranking BCE / overlap / alignment)
//  - y==0 blocks: per-element terms + per-batch reduction
//  - last block to finish: global combine -> out[0]
// Masked elements get SENT coordinates: any pair touching one contributes
// exactly 0 to overlap (iw<=0) and alignment (dist>=5 or dist==0), so the
// pair_valid product disappears from the hot loop (masks are binary).
// ---------------------------------------------------------------------------
__global__ void __launch_bounds__(256) k_all(
    const float* __restrict__ pnoise, const float* __restrict__ tnoise,
    const float* __restrict__ play,   const float* __restrict__ tlay,
    const float* __restrict__ mask,   float* __restrict__ out)
{
    __shared__ float  raw_p[NN * DD];   // 6 KB staging (reused for noise)
    __shared__ float  raw_t[NN * DD];   // used by y==0 blocks only
    __shared__ float4 sA[NN];           // x1, x2, y1, y2   (sentineled)
    __shared__ float4 sB[NN];           // ex, ey, p_layer, t_layer (ex/ey sentineled)
    __shared__ float  sC[NN];           // area = w*h (masked -> 0)
    __shared__ float  sh[8][12];
    __shared__ float  scx[BB], scy[BB], svc[BB], tot[12];
    __shared__ int    last;

    int b = blockIdx.x;
    int t = threadIdx.x;
    int wid = t >> 5, lane = t & 31;
    bool elemBlk = (blockIdx.y == 0);

    // ---- coalesced staging ----
    {
        const float4* p4 = (const float4*)(play + b * (NN * DD));
        float4* rp = (float4*)raw_p;
        rp[t] = p4[t];
        if (t < 128) rp[256 + t] = p4[256 + t];
        if (elemBlk) {
            const float4* t4 = (const float4*)(tlay + b * (NN * DD));
            float4* rt = (float4*)raw_t;
            rt[t] = t4[t];
            if (t < 128) rt[256 + t] = t4[256 + t];
        }
    }
    float m = mask[b * NN + t];
    float tl4;
    if (!elemBlk) tl4 = tlay[(b * NN + t) * DD + 4] * m;   // only col 4 needed
    __syncthreads();

    float pl0 = raw_p[t * 6 + 0] * m, pl1 = raw_p[t * 6 + 1] * m;
    float pl2 = raw_p[t * 6 + 2] * m, pl3 = raw_p[t * 6 + 3] * m;
    float pl4 = raw_p[t * 6 + 4] * m, pl5 = raw_p[t * 6 + 5] * m;
    if (elemBlk) tl4 = raw_t[t * 6 + 4] * m;

    float s = (m != 0.f) ? 0.f : SENT;     // masked values are 0, +s -> SENT
    sA[t] = make_float4(pl0 + s, pl0 + pl2 + s, pl1 + s, pl1 + pl3 + s);
    sB[t] = make_float4(pl0 + 0.5f * pl2 + s, pl1 + 0.5f * pl3 + s, pl4, tl4);
    sC[t] = pl2 * pl3;

    if (elemBlk) {
        // ---- element terms ----
        float tl0 = raw_t[t * 6 + 0] * m, tl1 = raw_t[t * 6 + 1] * m;
        float tl2 = raw_t[t * 6 + 2] * m, tl3 = raw_t[t * 6 + 3] * m;
        float tl5 = raw_t[t * 6 + 5] * m;

        float d0 = pl0 - tl0, d1 = pl1 - tl1, d2 = pl2 - tl2, d3 = pl3 - tl3;
        float mse4 = d0 * d0 + d1 * d1 + d2 * d2 + d3 * d3;

        float iw = fmaxf(fminf(pl0 + pl2, tl0 + tl2) - fmaxf(pl0, tl0), 0.f);
        float ih = fmaxf(fminf(pl1 + pl3, tl1 + tl3) - fmaxf(pl1, tl1), 0.f);
        float inter = iw * ih;
        float pa = pl2 * pl3, ta = tl2 * tl3;
        float iouL = 1.f - inter / (pa + ta - inter + EPSF);

        float lmse = (pl4 - tl4) * (pl4 - tl4);
        float cmse = (pl5 - tl5) * (pl5 - tl5);
        float gold = fabsf(pl2 / (pl3 + EPSF) - GOLDENF);
        float area = pl2 * pl3 * m;
        float cx = (pl0 + 0.5f * pl2) * m;
        float cy = (pl1 + 0.5f * pl3) * m;

        __syncthreads();      // sA/sB/sC + raw reads done; safe to restage
        {
            const float4* p4 = (const float4*)(pnoise + b * (NN * DD));
            const float4* t4 = (const float4*)(tnoise + b * (NN * DD));
            float4* rp = (float4*)raw_p;
            float4* rt = (float4*)raw_t;
            rp[t] = p4[t];
            rt[t] = t4[t];
            if (t < 128) { rp[256 + t] = p4[256 + t]; rt[256 + t] = t4[256 + t]; }
        }
        __syncthreads();
        float nl = 0.f;
#pragma unroll
        for (int d = 0; d < 6; d++) {
            float a = fabsf(raw_p[t * 6 + d] * m - raw_t[t * 6 + d] * m);
            nl += (a < 1.f) ? 0.5f * a * a : a - 0.5f;
        }

        float v[11] = {nl, mse4, iouL, lmse, cmse, gold,
                       area, area * area, cx, cy, m};
#pragma unroll
        for (int q = 0; q < 11; q++) {
            float sv = warpSum(v[q]);
            if (lane == 0) sh[wid][q] = sv;
        }
        __syncthreads();
        if (t < 11) {
            float sv = 0.f;
#pragma unroll
            for (int r = 0; r < 8; r++) sv += sh[r][t];
            g_batch[b][t] = sv;
            __threadfence();
        }
        __syncthreads();      // sh reused below
    } else {
        __syncthreads();      // publish sA/sB/sC
    }

    // ---- pairwise terms (mask-free inner loop, sentinel handles validity) ----
    int wkr = blockIdx.y * 256 + t;
    int rp  = wkr & 127;               // balanced row-pair
    int sub = wkr >> 7;                // [0, 2*SS)
    const int stride = 2 * SS;

    float rank = 0.f, ov = 0.f, al = 0.f;
    int rows[2] = {rp, NN - 1 - rp};
#pragma unroll
    for (int r = 0; r < 2; r++) {
        int i = rows[r];
        float4 Ai = sA[i];
        float4 Bi = sB[i];
        float ai = sC[i];
#pragma unroll 4
        for (int j = i + 1 + sub; j < NN; j += stride) {
            float4 A = sA[j];
            float4 Bv = sB[j];
            float aj = sC[j];

            // ranking BCE: d = p_j - p_i ; y = (t_i < t_j)
            float d = Bv.z - Bi.z;
            float base = __logf(1.f + __expf(-fabsf(d)));   // softplus(-|d|)
            float sg = (Bi.w < Bv.w) ? -d : d;
            rank += fminf(base + fmaxf(sg, 0.f), 100.f);

            // overlap ratio (sentinel forces iw<=0 for invalid pairs)
            float iw = fmaxf(fminf(Ai.y, A.y) - fmaxf(Ai.x, A.x), 0.f);
            float ih = fmaxf(fminf(Ai.w, A.w) - fmaxf(Ai.z, A.z), 0.f);
            ov += __fdividef(iw * ih, fminf(ai, aj) + EPSF);

            // alignment: 6 edges, penalty dist/5 if dist<5 (the /5 hoisted)
            float e0 = fabsf(Ai.x - A.x);
            float e1 = fabsf(Ai.y - A.y);
            float e2 = fabsf(Ai.z - A.z);
            float e3 = fabsf(Ai.w - A.w);
            float e4 = fabsf(Bi.x - Bv.x);
            float e5 = fabsf(Bi.y - Bv.y);
            float a6 = ((e0 < 5.f ? e0 : 0.f) + (e1 < 5.f ? e1 : 0.f))
                     + ((e2 < 5.f ? e2 : 0.f) + (e3 < 5.f ? e3 : 0.f))
                     + ((e4 < 5.f ? e4 : 0.f) + (e5 < 5.f ? e5 : 0.f));
            al += a6;
        }
    }
    al *= 0.2f;   // /ALIGN_THRESH hoisted

    float vv[3] = {rank, ov, al};
#pragma unroll
    for (int q = 0; q < 3; q++) {
        float sv = warpSum(vv[q]);
        if (lane == 0) sh[wid][q] = sv;
    }
    __syncthreads();
    if (t < 3) {
        float sv = 0.f;
#pragma unroll
        for (int r = 0; r < 8; r++) sv += sh[r][t];
        g_pair[b * SS + blockIdx.y][t] = sv;
        __threadfence();
    }
    __syncthreads();

    // ---- last-block finalization ----
    if (t == 0) last = (atomicAdd(&g_count, 1) == NBLK - 1);
    __syncthreads();
    if (!last) return;

    __threadfence();

    float v[12];
#pragma unroll
    for (int q = 0; q < 12; q++) v[q] = 0.f;

    if (t < BB) {
        const float* gb = g_batch[t];
        v[0] = gb[0]; v[1] = gb[1]; v[2] = gb[2];
        v[3] = gb[3]; v[4] = gb[4]; v[5] = gb[5];
        v[6] = gb[6];
        float sa = gb[6], sa2 = gb[7];
        float var = (sa2 - sa * sa * (1.f / (float)NN)) * (1.f / (float)(NN - 1));
        v[7] = sqrtf(fmaxf(var, 0.f));     // per-batch std, ddof=1
        scx[t] = gb[8]; scy[t] = gb[9]; svc[t] = gb[10];
    }
    v[8]  = g_pair[t][0] + g_pair[t + 256][0];
    v[9]  = g_pair[t][1] + g_pair[t + 256][1];
    v[10] = g_pair[t][2] + g_pair[t + 256][2];
    __syncthreads();

    // balance: faithful [B]/[B,1] broadcast -> B x B terms
    float bal = 0.f;
#pragma unroll
    for (int k = t; k < BB * BB; k += 256) {
        int i = k >> 6;
        int j = k & 63;
        float inv = 1.f / (svc[i] + EPSF);
        bal += (fabsf(scx[j] * inv - 512.f) + fabsf(scy[j] * inv - 512.f)) * (1.f / 512.f);
    }
    v[11] = bal;

#pragma unroll
    for (int q = 0; q < 12; q++) {
        float sv = warpSum(v[q]);
        if (lane == 0) sh[wid][q] = sv;
    }
    __syncthreads();
    if (t < 12) {
        float sv = 0.f;
#pragma unroll
        for (int r = 0; r < 8; r++) sv += sh[r][t];
        tot[t] = sv;
    }
    __syncthreads();

    if (t == 0) {
        const float BN = (float)(BB * NN);                 // 16384
        const float npairs = (float)NN * (NN - 1) * 0.5f;  // 32640

        float noise_loss = tot[0] / (BN * 6.f);
        float position_loss = tot[1] / (BN * 4.f) + 0.5f * (tot[2] / BN);
        float ranking = tot[8] / ((float)BB * npairs);
        float layer_loss = tot[3] / BN + 0.3f * ranking;
        float conf_loss = tot[4] / BN;
        float golden = tot[5] / BN;
        float mean_area = tot[6] / BN;
        float size_harm = (tot[7] / (float)BB) / (mean_area + EPSF);
        float balance = tot[11] / (float)(BB * BB);
        float aesthetic = 0.1f * golden + 0.2f * size_harm + 0.15f * balance;
        float overlap = tot[9] / ((float)BB * npairs);
        float align = tot[10] / ((float)BB * 6.f * npairs);

        out[0] = noise_loss + 1.0f * position_loss + 0.5f * layer_loss +
                 0.3f * conf_loss + 0.2f * aesthetic + 0.8f * overlap +
                 0.4f * align;

        g_count = 0;                   // reset for next graph replay
    }
}

extern "C" void kernel_launch(void* const* d_in, const int* in_sizes, int n_in,
                              void* d_out, int out_size)
{
    const float* pnoise = (const float*)d_in[0];
    const float* tnoise = (const float*)d_in[1];
    const float* play   = (const float*)d_in[2];
    const float* tlay   = (const float*)d_in[3];
    const float* mask   = (const float*)d_in[4];
    float* out = (float*)d_out;

    dim3 g(BB, SS);
    k_all<<<g, 256>>>(pnoise, tnoise, play, tlay, mask, out);
}